// round 7
// baseline (speedup 1.0000x reference)
#include <cuda_runtime.h>
#include <math.h>

#define Nn    10000
#define DEGc  16
#define Dn    17
#define E0    160000
#define ET    170000
#define FIN   512
#define H1    16
#define H2    32
#define NC    32
#define UMAX  160        // unique A-sums per column <= 17*18/2 = 153
#define PAD   2          // sA row padding (floats): stride gcd with 32 = 2

typedef unsigned long long u64;

// ---------------- scratch (device globals; no allocation allowed) ----------
__device__ __align__(256) float g_g1[Nn * H1];
__device__ __align__(256) float g_g2[Nn * H2];
__device__ float g_c1[ET];
__device__ float g_c2[ET];
__device__ int   g_map[Dn * Dn];   // (e,j) -> unique-sum rank
__device__ int   g_Ssum[UMAX];     // unique offset sums
__device__ int   g_bidx[Dn];       // k -> unique rank of offset O_k
__device__ int   g_U;              // count of unique sums

// ---------------- packed-f32x2 helpers -------------------------------------
__device__ __forceinline__ u64 fma2(u64 a, u64 b, u64 c) {
    u64 d; asm("fma.rn.f32x2 %0, %1, %2, %3;" : "=l"(d) : "l"(a), "l"(b), "l"(c)); return d;
}
__device__ __forceinline__ u64 add2(u64 a, u64 b) {
    u64 d; asm("add.rn.f32x2 %0, %1, %2;" : "=l"(d) : "l"(a), "l"(b)); return d;
}
__device__ __forceinline__ float ex2a(float x) {
    float r; asm("ex2.approx.ftz.f32 %0, %1;" : "=f"(r) : "f"(x)); return r;
}
__device__ __forceinline__ void lds2(const float* p, u64& a, u64& b) {
    unsigned s = (unsigned)__cvta_generic_to_shared(p);
    asm("ld.shared.v2.u64 {%0,%1}, [%2];" : "=l"(a), "=l"(b) : "r"(s));
}
__device__ __forceinline__ u64 lds1(const float* p) {
    unsigned s = (unsigned)__cvta_generic_to_shared(p);
    u64 v; asm("ld.shared.b64 %0, [%1];" : "=l"(v) : "r"(s)); return v;
}
__device__ __forceinline__ float hsum2(u64 v) {
    float lo, hi;
    asm("mov.b64 {%0,%1}, %2;" : "=f"(lo), "=f"(hi) : "l"(v));
    return lo + hi;
}

#define LOG2E10 14.4269504089f   //  10 * log2(e)
#define LOG2E20 28.8539008177f   //  20 * log2(e)

// ---------------- K0: build unique-sum tables (once per launch) ------------
__global__ void k_setup(const int* __restrict__ rows) {
    __shared__ int O[Dn];
    __shared__ int S[Dn * Dn];
    __shared__ int first[Dn * Dn];
    const int t = threadIdx.x;            // 320 threads
    if (t < Dn) O[t] = (t < DEGc) ? rows[t] : 0;
    __syncthreads();
    if (t < Dn * Dn) {
        int e = t / Dn, j = t - (t / Dn) * Dn;
        int s = O[e] + O[j]; if (s >= Nn) s -= Nn;
        S[t] = s;
    }
    __syncthreads();
    if (t < Dn * Dn) {
        int f = 0;
        while (S[f] != S[t]) f++;
        first[t] = f;
    }
    __syncthreads();
    if (t < Dn * Dn) {
        int r = 0;
        for (int i = 0; i < first[t]; i++) r += (first[i] == i);
        g_map[t] = r;
        if (first[t] == t) g_Ssum[r] = S[t];
        if ((t % Dn) == Dn - 1) g_bidx[t / Dn] = r;   // (e=k, j=self) -> rank of O_k
    }
    __syncthreads();
    if (t == 0) {
        int u = 0;
        for (int i = 0; i < Dn * Dn; i++) u += (first[i] == i);
        g_U = u;
    }
}

// ---------------- K1: g1 = x @ W1 + b1 -------------------------------------
__global__ void k_gemm1(const float* __restrict__ x,
                        const float* __restrict__ W1,
                        const float* __restrict__ b1) {
    __shared__ float sW[FIN * H1];   // 32 KB
    __shared__ float sX[16][128];    // 8 KB
    const int t = threadIdx.x;
    for (int idx = t; idx < FIN * H1; idx += 256) sW[idx] = W1[idx];
    const int rowBase = blockIdx.x * 16;
    const int il = t >> 4, j = t & 15;
    float acc = b1[j];
    for (int k0 = 0; k0 < FIN; k0 += 128) {
        __syncthreads();
        for (int idx = t; idx < 16 * 128; idx += 256) {
            int r = idx >> 7, c = idx & 127;
            sX[r][c] = x[(rowBase + r) * FIN + k0 + c];
        }
        __syncthreads();
        float a0 = 0.f, a1 = 0.f;
        #pragma unroll
        for (int k = 0; k < 128; k += 2) {
            a0 += sX[il][k]     * sW[(k0 + k) * H1 + j];
            a1 += sX[il][k + 1] * sW[(k0 + k + 1) * H1 + j];
        }
        acc += a0 + a1;
    }
    g_g1[(rowBase + il) * H1 + j] = acc;
}

// ---------------- deduped cross core: 2 A-rows per lane --------------------
// R[u] = sum_k exp(-10*||h_{c+S_u} - h_{b_k}||^2), norms computed on-chip.
template <int H, int NT>
__device__ __forceinline__ void crossD_core(const float* __restrict__ g,
                                            const int* __restrict__ rows,
                                            int c, int t,
                                            float (*sB)[H], float* sA,
                                            float* ssqa, int* sbid, float* R) {
    const int U  = g_U;
    const int UH = (U + 1) >> 1;
    if (t < Dn) sbid[t] = g_bidx[t];
    // stage B rows (17 rows, coalesced per row)
    for (int idx = t; idx < Dn * H; idx += NT) {
        int k = idx / H, h = idx - k * H;
        int nk = (k < DEGc) ? rows[c * DEGc + k] : c;
        sB[k][h] = g[nk * H + h];
    }
    // stage all unique A rows, fully coalesced float loads
    for (int idx = t; idx < U * H; idx += NT) {
        int row = idx / H, h = idx - row * H;
        int an = c + g_Ssum[row]; if (an >= Nn) an -= Nn;
        sA[row * (H + PAD) + h] = g[an * H + h];
    }
    __syncthreads();

    u64 a0[H / 2], a1[H / 2];
    float sqa0 = 0.f, sqa1 = 0.f;
    bool has1 = false;
    if (t < UH) {
        const int t1 = t + UH;
        has1 = (t1 < U);
        const float* r0 = sA + t * (H + PAD);
        const float* r1 = sA + (has1 ? t1 : t) * (H + PAD);
        #pragma unroll
        for (int q = 0; q < H / 2; q++) { a0[q] = lds1(r0 + 2 * q); a1[q] = lds1(r1 + 2 * q); }
        u64 n00 = 0, n01 = 0, n10 = 0, n11 = 0;
        #pragma unroll
        for (int q = 0; q < H / 2; q += 2) {
            n00 = fma2(a0[q], a0[q], n00); n01 = fma2(a0[q + 1], a0[q + 1], n01);
            n10 = fma2(a1[q], a1[q], n10); n11 = fma2(a1[q + 1], a1[q + 1], n11);
        }
        sqa0 = LOG2E10 * hsum2(add2(n00, n01));
        sqa1 = LOG2E10 * hsum2(add2(n10, n11));
        ssqa[t] = sqa0;
        if (has1) ssqa[t1] = sqa1;
    }
    __syncthreads();

    if (t < UH) {
        float s0 = 0.f, s1 = 0.f;
        #pragma unroll
        for (int k = 0; k < Dn; k++) {
            const float* bp = sB[k];
            const float sqb = ssqa[sbid[k]];
            u64 p00 = 0, p01 = 0, p10 = 0, p11 = 0;
            #pragma unroll
            for (int q = 0; q < H / 2; q += 2) {
                u64 b0, b1;
                lds2(bp + 2 * q, b0, b1);
                p00 = fma2(a0[q],     b0, p00);
                p01 = fma2(a0[q + 1], b1, p01);
                p10 = fma2(a1[q],     b0, p10);
                p11 = fma2(a1[q + 1], b1, p11);
            }
            float dot0 = hsum2(add2(p00, p01));
            float dot1 = hsum2(add2(p10, p11));
            s0 += ex2a(fmaf(dot0, LOG2E20, -(sqa0 + sqb)));
            s1 += ex2a(fmaf(dot1, LOG2E20, -(sqa1 + sqb)));
        }
        R[t] = s0;
        if (has1) R[t + UH] = s1;
    }
    __syncthreads();
}

// ---------------- K2: layer-1 cross means, fused agg+relu+W2 ---------------
__global__ void __launch_bounds__(96, 8) k_cross1(const int* __restrict__ rows,
                                                  const float* __restrict__ W2,
                                                  const float* __restrict__ b2) {
    __shared__ __align__(16) float sB[Dn][H1];
    __shared__ __align__(16) float sA[UMAX * (H1 + PAD)];
    __shared__ float ssqa[UMAX];
    __shared__ int   sbid[Dn];
    __shared__ float R[UMAX];
    __shared__ float sW2[H1 * NC];
    const int c = blockIdx.x, t = threadIdx.x;
    for (int i = t; i < H1 * NC; i += 96) sW2[i] = W2[i];
    crossD_core<H1, 96>(g_g1, rows, c, t, sB, sA, ssqa, sbid, R);

    if (t < Dn) {                              // per-edge cross means
        const int* mp = g_map + t * Dn;
        float s = 0.f;
        #pragma unroll
        for (int j = 0; j < Dn; j++) s += R[mp[j]];
        g_c1[(t < DEGc) ? (c * DEGc + t) : (E0 + c)] = s * (1.0f / (Dn * Dn));
    }
    if (t >= 32 && t < 64) {                   // fused GCN agg + relu + @W2+b2
        const int l = t - 32;
        float rv = 0.f;
        if (l < H1) {
            float acc = 0.f;
            #pragma unroll
            for (int k = 0; k < Dn; k++) acc += sB[k][l];
            rv = fmaxf(acc * (1.0f / 17.0f), 0.f);
        }
        float acc = b2[l];
        #pragma unroll
        for (int h = 0; h < H1; h++) {
            float rh = __shfl_sync(0xffffffffu, rv, h);
            acc += rh * sW2[h * NC + l];
        }
        g_g2[c * NC + l] = acc;
    }
}

// ---------------- K3: layer-2 cross means, fused agg + log_softmax ---------
__global__ void __launch_bounds__(96, 6) k_cross2(const int* __restrict__ rows,
                                                  float* __restrict__ out) {
    __shared__ __align__(16) float sB[Dn][H2];
    __shared__ __align__(16) float sA[UMAX * (H2 + PAD)];
    __shared__ float ssqa[UMAX];
    __shared__ int   sbid[Dn];
    __shared__ float R[UMAX];
    const int c = blockIdx.x, t = threadIdx.x;
    crossD_core<H2, 96>(g_g2, rows, c, t, sB, sA, ssqa, sbid, R);

    if (t < Dn) {
        const int* mp = g_map + t * Dn;
        float s = 0.f;
        #pragma unroll
        for (int j = 0; j < Dn; j++) s += R[mp[j]];
        g_c2[(t < DEGc) ? (c * DEGc + t) : (E0 + c)] = s * (1.0f / (Dn * Dn));
    }
    if (t >= 32 && t < 64) {                   // fused GCN agg + log_softmax
        const int l = t - 32;
        float acc = 0.f;
        #pragma unroll
        for (int k = 0; k < Dn; k++) acc += sB[k][l];
        acc *= (1.0f / 17.0f);
        float m = acc;
        #pragma unroll
        for (int d = 16; d >= 1; d >>= 1) m = fmaxf(m, __shfl_xor_sync(0xffffffffu, m, d));
        float ex = __expf(acc - m);
        float s = ex;
        #pragma unroll
        for (int d = 16; d >= 1; d >>= 1) s += __shfl_xor_sync(0xffffffffu, s, d);
        out[c * NC + l] = acc - m - logf(s);
    }
}

// ---------------- K4: assemble both MMD outputs ----------------------------
__global__ void k_mmd(const int* __restrict__ rows, const int* __restrict__ cols,
                      float* __restrict__ m1, float* __restrict__ m2) {
    int e = blockIdx.x * blockDim.x + threadIdx.x;
    if (e >= ET) return;
    int r, cc;
    if (e < E0) { r = rows[e]; cc = cols[e]; } else { r = cc = e - E0; }
    m1[e] = g_c1[E0 + r] + g_c1[E0 + cc] - 2.0f * g_c1[e];
    m2[e] = g_c2[E0 + r] + g_c2[E0 + cc] - 2.0f * g_c2[e];
}

// ---------------- launch ---------------------------------------------------
extern "C" void kernel_launch(void* const* d_in, const int* in_sizes, int n_in,
                              void* d_out, int out_size) {
    const float* x  = (const float*)d_in[0];
    const int*   ei = (const int*)d_in[1];
    const float* W1 = (const float*)d_in[2];
    const float* b1 = (const float*)d_in[3];
    const float* W2 = (const float*)d_in[4];
    const float* b2 = (const float*)d_in[5];
    float* out = (float*)d_out;

    const int* rows = ei;
    const int* cols = ei + E0;

    k_setup<<<1, 320>>>(rows);
    k_gemm1<<<Nn / 16, 256>>>(x, W1, b1);
    k_cross1<<<Nn, 96>>>(rows, W2, b2);
    k_cross2<<<Nn, 96>>>(rows, out);
    k_mmd<<<(ET + 255) / 256, 256>>>(rows, cols, out + Nn * NC, out + Nn * NC + ET);
}